// round 4
// baseline (speedup 1.0000x reference)
#include <cuda_runtime.h>

#define SS 512
#define NUNITS 9
#define DSTRIDE 520   // 512 + 8 zero pad, float4-aligned rows
#define MAXB 128

__device__ float g_diag[MAXB * DSTRIDE];
__device__ float g_bias[SS * SS];

// Fused prep: low blocks reduce bias (streams 9.4 MB), high blocks gather the
// diagonals (row-activation latency bound) — overlapped in one launch.
__global__ void prep_kernel(const float* __restrict__ in,
                            const float* __restrict__ bb,
                            int B, int nbias_blocks) {
    if (blockIdx.x < (unsigned)nbias_blocks) {
        int t4 = blockIdx.x * blockDim.x + threadIdx.x;
        if (t4 >= (SS * SS) / 4) return;
        const float4* bp = (const float4*)(bb + (size_t)t4 * 36);
        float v[36];
#pragma unroll
        for (int k = 0; k < 9; k++) {
            float4 q = bp[k];
            v[k * 4 + 0] = q.x; v[k * 4 + 1] = q.y;
            v[k * 4 + 2] = q.z; v[k * 4 + 3] = q.w;
        }
        float4 s;
        float* sp = (float*)&s;
#pragma unroll
        for (int jj = 0; jj < 4; jj++) {
            float acc = 0.0f;
#pragma unroll
            for (int t = 0; t < 9; t++) acc += v[jj * 9 + t];
            sp[jj] = acc;
        }
        *(float4*)(g_bias + (size_t)t4 * 4) = s;
    } else {
        int idx = (blockIdx.x - nbias_blocks) * blockDim.x + threadIdx.x;
        int total = B * DSTRIDE;
        if (idx >= total) return;
        int b = idx / DSTRIDE;
        int j = idx - b * DSTRIDE;
        float v = 0.0f;
        if (j < SS) v = in[(size_t)b * SS * SS + (size_t)j * (SS + 1)];
        g_diag[idx] = v;
    }
}

// Main kernel: thread owns TWO i-rows (i0, i0+1) x one j-quad. The diag
// window depends only on j, so 3 LDG.128 now feed 8 outputs (2 STG.128):
// L1 wavefronts per output byte drop 1.6x vs the 1-row version.
__global__ __launch_bounds__(128, 4)
void cnn_kernel(const float* __restrict__ w,
                float* __restrict__ out,
                int B, int bper) {
    int i0 = blockIdx.x * 2;      // 0,2,...,510
    int i1 = i0 + 1;
    int j0 = threadIdx.x << 2;    // 0,4,...,508
    int b0 = blockIdx.y * bper;
    int b1 = b0 + bper;
    if (b1 > B) b1 = B;
    if (b0 >= b1) return;

    // ---- prologue: 18x LDG.128 weights + 2x LDG.128 bias sums ----
    float wa[36], wb[36];
    const float4* wpa = (const float4*)(w + ((size_t)i0 * SS + j0) * NUNITS);
    const float4* wpb = (const float4*)(w + ((size_t)i1 * SS + j0) * NUNITS);
#pragma unroll
    for (int k = 0; k < 9; k++) {
        float4 qa = wpa[k];
        wa[k * 4 + 0] = qa.x; wa[k * 4 + 1] = qa.y;
        wa[k * 4 + 2] = qa.z; wa[k * 4 + 3] = qa.w;
        float4 qb = wpb[k];
        wb[k * 4 + 0] = qb.x; wb[k * 4 + 1] = qb.y;
        wb[k * 4 + 2] = qb.z; wb[k * 4 + 3] = qb.w;
    }
#pragma unroll
    for (int n = 0; n < 36; n++) {
        int t = n % 9;                       // compile-time per n
        wa[n] *= (i0 + (t / 3) < SS) ? 9.0f : 0.0f;
        wb[n] *= (i1 + (t / 3) < SS) ? 9.0f : 0.0f;
    }
    float4 biasa = *(const float4*)(g_bias + (size_t)i0 * SS + j0);
    float4 biasb = *(const float4*)(g_bias + (size_t)i1 * SS + j0);

    const float4* dq = (const float4*)(g_diag + (size_t)b0 * DSTRIDE + j0);
    float* opa = out + (size_t)b0 * (SS * SS) + (size_t)i0 * SS + j0;

    for (int b = b0; b < b1; ++b) {
        float4 c0 = dq[0], c1 = dq[1], c2 = dq[2];
        dq += DSTRIDE / 4;

        float d[12] = {c0.x, c0.y, c0.z, c0.w,
                       c1.x, c1.y, c1.z, c1.w,
                       c2.x, c2.y, c2.z, c2.w};

        float a0 = biasa.x, a1 = biasa.y, a2 = biasa.z, a3 = biasa.w;
        float e0 = biasb.x, e1 = biasb.y, e2 = biasb.z, e3 = biasb.w;
#pragma unroll
        for (int t = 0; t < 9; t++) {
            a0 = fmaf(d[t],     wa[t],      a0);
            a1 = fmaf(d[t + 1], wa[9 + t],  a1);
            a2 = fmaf(d[t + 2], wa[18 + t], a2);
            a3 = fmaf(d[t + 3], wa[27 + t], a3);
            e0 = fmaf(d[t],     wb[t],      e0);
            e1 = fmaf(d[t + 1], wb[9 + t],  e1);
            e2 = fmaf(d[t + 2], wb[18 + t], e2);
            e3 = fmaf(d[t + 3], wb[27 + t], e3);
        }
        float4 oa; oa.x = a0; oa.y = a1; oa.z = a2; oa.w = a3;
        float4 ob; ob.x = e0; ob.y = e1; ob.z = e2; ob.w = e3;
        *(float4*)opa        = oa;
        *(float4*)(opa + SS) = ob;
        opa += SS * SS;
    }
}

extern "C" void kernel_launch(void* const* d_in, const int* in_sizes, int n_in,
                              void* d_out, int out_size) {
    const float* in = (const float*)d_in[0];   // inputs (B,512,512,1) f32
    const float* w  = (const float*)d_in[1];   // w (512*512*9,) f32
    const float* bb = (const float*)d_in[2];   // b (512*512*9,) f32
    float* out = (float*)d_out;                // (B, 512*512) f32

    int B = in_sizes[0] / (SS * SS);
    if (B > MAXB) B = MAXB;

    {
        int nbias_blocks = ((SS * SS) / 4 + 255) / 256;   // 256
        int ndiag_blocks = (B * DSTRIDE + 255) / 256;     // ~204
        prep_kernel<<<nbias_blocks + ndiag_blocks, 256>>>(in, bb, B, nbias_blocks);
    }

    const int NSLICE = 5;
    int bper = (B + NSLICE - 1) / NSLICE;
    dim3 grid(SS / 2, NSLICE);                // 256 x 5 = 1280 blocks
    cnn_kernel<<<grid, 128>>>(w, out, B, bper);
}